// round 16
// baseline (speedup 1.0000x reference)
#include <cuda_runtime.h>
#include <cstdint>

// out[b,l,h] = data[b,l,h] * mask(b,l)
//   mask = l < a_end      -> 1 - (a_end - l)/C
//          elif l < s_len -> 1 - (l - a_idx)/C
//          else           -> 0
// B=512, L=512, H=100, C=40.
// Index arrays are int32 (JAX x32 downcasts the requested int64).
//
// R7 per-thread structure (KPT=4 front-batched predicated loads, dead-row
// read skip, ~28 regs) at THREADS=128 -> grid 12800: same per-warp MLP,
// 2x finer CTA granularity for the bimodal live/dead work distribution,
// halved per-CTA L1tex load burst (lower cross-CTA spread).

#define B_DIM 512
#define L_DIM 512
#define H_DIM 100
#define VEC_PER_ROW (H_DIM / 4)                      // 25
#define TOTAL_VEC (B_DIM * L_DIM * VEC_PER_ROW)      // 6,553,600
#define KPT 4
#define THREADS 128
#define VPB (THREADS * KPT)                          // 512
#define BLOCKS (TOTAL_VEC / VPB)                     // 12800, exact

#define C_INV (1.0f / 40.0f)

__device__ __forceinline__ float row_mask(int l, int a_idx, int a_end, int s_len)
{
    float i_f = (float)l;
    if (l < a_end)  return 1.0f - ((float)a_end - i_f) * C_INV;
    if (l < s_len)  return 1.0f - (i_f - (float)a_idx) * C_INV;
    return 0.0f;
}

__global__ __launch_bounds__(THREADS) void mask_mul_kernel(
    const float4* __restrict__ data,
    const int* __restrict__ aspect_index,
    const int* __restrict__ aspect_len,
    const int* __restrict__ sents_len,
    float4* __restrict__ out)
{
    int base = blockIdx.x * VPB + threadIdx.x;

    // Phase 1: masks from cache-resident index arrays (no stream traffic).
    float m[KPT];
#pragma unroll
    for (int k = 0; k < KPT; k++) {
        int idx = base + k * THREADS;
        int row = idx / VEC_PER_ROW;         // b*L + l  (const div -> mulhi)
        int b = row >> 9;                    // / L_DIM
        int l = row & (L_DIM - 1);
        int a_idx = __ldg(&aspect_index[b]);
        int a_end = a_idx + __ldg(&aspect_len[b]);
        int s_len = __ldg(&sents_len[b]);
        m[k] = row_mask(l, a_idx, a_end, s_len);
    }

    // Phase 2: predicated front-batched stream loads (skip dead rows).
    float4 v[KPT];
#pragma unroll
    for (int k = 0; k < KPT; k++) {
        if (m[k] != 0.0f) {
            v[k] = data[base + k * THREADS];
        } else {
            v[k] = make_float4(0.0f, 0.0f, 0.0f, 0.0f);
        }
    }

    // Phase 3: scale + store (store always: out is poisoned before timing).
#pragma unroll
    for (int k = 0; k < KPT; k++) {
        v[k].x *= m[k]; v[k].y *= m[k]; v[k].z *= m[k]; v[k].w *= m[k];
        out[base + k * THREADS] = v[k];
    }
}

extern "C" void kernel_launch(void* const* d_in, const int* in_sizes, int n_in,
                              void* d_out, int out_size)
{
    const float4* data = (const float4*)d_in[0];
    const int*    aidx = (const int*)d_in[1];
    const int*    alen = (const int*)d_in[2];
    const int*    slen = (const int*)d_in[3];
    float4* out = (float4*)d_out;

    mask_mul_kernel<<<BLOCKS, THREADS>>>(data, aidx, alen, slen, out);
}